// round 5
// baseline (speedup 1.0000x reference)
#include <cuda_runtime.h>

// Problem constants
#define BB   8
#define SEQ  2047
#define LL   2048     // SEQ + 1 (CLS prepended)
#define HH   256
#define NH   8
#define DD   32
#define VV   32001
#define NCH  32       // t-chunks for ybar
#define CHT  64       // tokens per chunk

// ---------------- scratch (static device globals; no allocation) -------------
__device__ int   g_is64;
__device__ float g_pe[LL * HH];                 // 2 MB positional encoding
__device__ float g_qk[NH * HH];                 // per-head folded query vectors (scaled)
__device__ float g_y0[HH];                      // y at position 0 (same for all b)
__device__ float g_se[VV * NH];                 // ~1 MB: qk . emb[v], layout [v][n]
__device__ float g_pescT[LL * NH];              // qk . pe[t], layout [t][n]
__device__ float g_zp[BB * NH * NCH];           // partition-function partials
__device__ float g_ybp[NCH * BB * NH * HH];     // weighted-sum partials (2 MB)
__device__ float g_yfin[BB * HH];               // final hidden at position 0

// ---------------- fused: dtype detect (block 8) + per-head prep (blocks 0-7) --
__global__ void k_init(const unsigned int* __restrict__ xw,
                       const float* __restrict__ emb,
                       const float* __restrict__ wq,
                       const float* __restrict__ wk) {
    int blk = blockIdx.x;
    int tid = threadIdx.x;       // 256

    if (blk == NH) {             // ---- dtype detection ----
        __shared__ int bad;
        if (tid == 0) bad = 0;
        __syncthreads();
        for (int i = tid; i < 1024; i += 256)
            if (xw[2 * i + 1] != 0u) bad = 1;
        __syncthreads();
        if (tid == 0) g_is64 = bad ? 0 : 1;
        return;
    }

    int n = blk;
    __shared__ float y0s[HH];
    __shared__ float q0s[DD];

    float y0 = emb[2 * HH + tid] + ((tid & 1) ? 1.0f : 0.0f);   // pe[0]=[0,1,0,1..]
    y0s[tid] = y0;
    if (n == 0) g_y0[tid] = y0;
    __syncthreads();

    if (tid < DD) {
        const float* wqr = wq + (size_t)(n * DD + tid) * HH;
        float a = 0.f;
        #pragma unroll 8
        for (int h = 0; h < HH; h++) a += y0s[h] * wqr[h];
        q0s[tid] = a;
    }
    __syncthreads();

    const float scale = 0.17677669529663687f;   // 1/sqrt(32)
    float s = 0.f;
    #pragma unroll
    for (int k = 0; k < DD; k++)
        s += q0s[k] * wk[(size_t)(n * DD + k) * HH + tid];
    g_qk[n * HH + tid] = s * scale;
}

// ---------------- fused: pe table + pescT (blocks < LL) + se GEMV (rest) ------
__global__ void __launch_bounds__(256) k_mid(const float* __restrict__ emb) {
    int tid = threadIdx.x, lane = tid & 31, warp = tid >> 5;

    if (blockIdx.x < LL) {
        int t = blockIdx.x;
        __shared__ float row[HH];
        if (tid < 128) {
            float div = expf(-(float)(2 * tid) * 0.03597789203f);   // ln(10000)/256
            float s, c;
            sincosf((float)t * div, &s, &c);
            row[2 * tid]     = s;
            row[2 * tid + 1] = c;
            g_pe[(size_t)t * HH + 2 * tid]     = s;
            g_pe[(size_t)t * HH + 2 * tid + 1] = c;
        }
        __syncthreads();
        int n = warp;
        float p = 0.f;
        #pragma unroll
        for (int j = lane; j < HH; j += 32) p += g_qk[n * HH + j] * row[j];
        #pragma unroll
        for (int off = 16; off; off >>= 1) p += __shfl_xor_sync(~0u, p, off);
        if (lane == 0) g_pescT[t * NH + n] = p;
        return;
    }

    __shared__ float qks[NH * HH];
    for (int i = tid; i < NH * HH; i += 256) qks[i] = g_qk[i];
    __syncthreads();

    int v0 = (blockIdx.x - LL) * 16 + warp * 2;   // two rows per warp
    int v1 = v0 + 1;
    if (v0 >= VV) return;
    bool has1 = (v1 < VV);

    const float4* e40 = (const float4*)(emb + (size_t)v0 * HH);
    const float4* e41 = (const float4*)(emb + (size_t)(has1 ? v1 : v0) * HH);
    float4 a0 = e40[lane];
    float4 b0 = e40[lane + 32];
    float4 a1 = e41[lane];
    float4 b1 = e41[lane + 32];

    float p0[8], p1[8];
    #pragma unroll
    for (int n = 0; n < 8; n++) {
        const float4* q4 = (const float4*)(qks + n * HH);
        float4 qa = q4[lane], qb = q4[lane + 32];
        p0[n] = a0.x * qa.x + a0.y * qa.y + a0.z * qa.z + a0.w * qa.w
              + b0.x * qb.x + b0.y * qb.y + b0.z * qb.z + b0.w * qb.w;
        p1[n] = a1.x * qa.x + a1.y * qa.y + a1.z * qa.z + a1.w * qa.w
              + b1.x * qb.x + b1.y * qb.y + b1.z * qb.z + b1.w * qb.w;
    }
    // funnel both rows: 8 values x 32 lanes -> 5 shuffles each
    #pragma unroll
    for (int n = 0; n < 4; n++) {
        bool hi = (lane & 8) != 0;
        float k0 = hi ? p0[n + 4] : p0[n], s0 = hi ? p0[n] : p0[n + 4];
        float k1 = hi ? p1[n + 4] : p1[n], s1 = hi ? p1[n] : p1[n + 4];
        p0[n] = k0 + __shfl_xor_sync(~0u, s0, 8);
        p1[n] = k1 + __shfl_xor_sync(~0u, s1, 8);
    }
    #pragma unroll
    for (int n = 0; n < 2; n++) {
        bool hi = (lane & 4) != 0;
        float k0 = hi ? p0[n + 2] : p0[n], s0 = hi ? p0[n] : p0[n + 2];
        float k1 = hi ? p1[n + 2] : p1[n], s1 = hi ? p1[n] : p1[n + 2];
        p0[n] = k0 + __shfl_xor_sync(~0u, s0, 4);
        p1[n] = k1 + __shfl_xor_sync(~0u, s1, 4);
    }
    {
        bool hi = (lane & 2) != 0;
        float k0 = hi ? p0[1] : p0[0], s0 = hi ? p0[0] : p0[1];
        float k1 = hi ? p1[1] : p1[0], s1 = hi ? p1[0] : p1[1];
        p0[0] = k0 + __shfl_xor_sync(~0u, s0, 2);
        p1[0] = k1 + __shfl_xor_sync(~0u, s1, 2);
    }
    p0[0] += __shfl_xor_sync(~0u, p0[0], 16);
    p0[0] += __shfl_xor_sync(~0u, p0[0], 1);
    p1[0] += __shfl_xor_sync(~0u, p1[0], 16);
    p1[0] += __shfl_xor_sync(~0u, p1[0], 1);
    float r0 = __shfl_sync(~0u, p0[0], (lane & 7) * 2);
    float r1 = __shfl_sync(~0u, p1[0], (lane & 7) * 2);
    if (lane < 8) g_se[(size_t)v0 * NH + lane] = r0;
    else if (lane < 16 && has1) g_se[(size_t)v1 * NH + (lane - 8)] = r1;
}

// ---------------- fused scores+exp+weighted-sum partials ----------------------
// grid (NCH chunks, BB batches), 256 threads
__global__ void __launch_bounds__(256) k_ybar(const void* __restrict__ xraw,
                                              const float* __restrict__ emb) {
    __shared__ float A8[8][CHT];
    __shared__ int toks[CHT];
    int tid = threadIdx.x, lane = tid & 31, warp = tid >> 5;
    int ch = blockIdx.x;
    int b  = blockIdx.y;
    int c0 = ch * CHT;
    int is64 = g_is64;

    // Phase A: tokens, scores, exp (unnormalized; scores are O(1), safe)
    if (tid < CHT) {
        int t = c0 + tid;
        int tok;
        if (t == 0) tok = 2;
        else if (is64) tok = (int)((const long long*)xraw)[(size_t)b * SEQ + t - 1];
        else           tok = ((const int*)xraw)[(size_t)b * SEQ + t - 1];
        toks[tid] = tok;

        const float4* se4 = (const float4*)(g_se + (size_t)tok * NH);
        const float4* pp4 = (const float4*)(g_pescT + (size_t)t * NH);
        float4 s0 = se4[0], s1 = se4[1];
        float4 p0 = pp4[0], p1 = pp4[1];
        A8[0][tid] = expf(s0.x + p0.x);
        A8[1][tid] = expf(s0.y + p0.y);
        A8[2][tid] = expf(s0.z + p0.z);
        A8[3][tid] = expf(s0.w + p0.w);
        A8[4][tid] = expf(s1.x + p1.x);
        A8[5][tid] = expf(s1.y + p1.y);
        A8[6][tid] = expf(s1.z + p1.z);
        A8[7][tid] = expf(s1.w + p1.w);
    }
    __syncthreads();

    // Phase B: per-head partition partials (warp n reduces A8[n][:])
    {
        float z = A8[warp][lane] + A8[warp][lane + 32];
        #pragma unroll
        for (int off = 16; off; off >>= 1) z += __shfl_xor_sync(~0u, z, off);
        if (lane == 0) g_zp[((size_t)b * NH + warp) * NCH + ch] = z;
    }

    // Phase C: weighted sums over tokens (tid = h), 8-deep load batching
    int h = tid;
    float acc[8] = {0.f, 0.f, 0.f, 0.f, 0.f, 0.f, 0.f, 0.f};
    #pragma unroll
    for (int tt = 0; tt < CHT; tt += 8) {
        float ev[8], pv[8];
        #pragma unroll
        for (int j = 0; j < 8; j++) {
            ev[j] = emb[(size_t)toks[tt + j] * HH + h];
            pv[j] = g_pe[(size_t)(c0 + tt + j) * HH + h];
        }
        #pragma unroll
        for (int j = 0; j < 8; j++) {
            float y = ev[j] + pv[j];
            #pragma unroll
            for (int n = 0; n < 8; n++) acc[n] += A8[n][tt + j] * y;
        }
    }
    #pragma unroll
    for (int n = 0; n < 8; n++)
        g_ybp[((size_t)ch * BB + b) * (NH * HH) + n * HH + h] = acc[n];
}

// ---------------- k_ov: reduce+normalize, V-proj, O-proj, residual ------------
// grid BB = 8 blocks, 512 threads
__global__ void __launch_bounds__(512) k_ov(const float* __restrict__ wv,
                                            const float* __restrict__ wo) {
    __shared__ __align__(16) float ybs[NH * HH];  // 8 KB
    __shared__ __align__(16) float os[HH];
    __shared__ float zinv[NH];
    int tid = threadIdx.x, lane = tid & 31, warp = tid >> 5;
    int b = blockIdx.x;

    // partition functions: warp n (n<8) reduces its 32 chunk partials
    if (warp < NH) {
        float z = g_zp[((size_t)b * NH + warp) * NCH + lane];
        #pragma unroll
        for (int off = 16; off; off >>= 1) z += __shfl_xor_sync(~0u, z, off);
        if (lane == 0) zinv[warp] = 1.f / z;
    }

    // reduce ybp over 32 chunks, high MLP via explicit prefetch
    float sred[4];
    #pragma unroll
    for (int r = 0; r < 4; r++) {
        int i = tid + r * 512;
        float s = 0.f;
        #pragma unroll
        for (int cg = 0; cg < NCH; cg += 8) {
            float v[8];
            #pragma unroll
            for (int j = 0; j < 8; j++)
                v[j] = g_ybp[((size_t)(cg + j) * BB + b) * (NH * HH) + i];
            #pragma unroll
            for (int j = 0; j < 8; j++) s += v[j];
        }
        sred[r] = s;
    }
    __syncthreads();   // zinv ready
    #pragma unroll
    for (int r = 0; r < 4; r++) {
        int i = tid + r * 512;
        ybs[i] = sred[r] * zinv[i >> 8];
    }
    __syncthreads();

    // V projection: os[row] = ybar[n,:] . wv[row,:], row = n*32+k
    // 2 threads per row (split h in halves), 512 threads -> 256 rows
    {
        int row = tid >> 1, half = tid & 1;
        int n = row >> 5;
        const float4* wvr = (const float4*)(wv + (size_t)row * HH) + half * 32;
        const float4* ybr = (const float4*)(ybs + n * HH) + half * 32;
        float a = 0.f;
        #pragma unroll
        for (int c = 0; c < 32; c++) {
            float4 w = wvr[c]; float4 y = ybr[c];
            a += w.x * y.x + w.y * y.y + w.z * y.z + w.w * y.w;
        }
        a += __shfl_xor_sync(~0u, a, 1);
        if (half == 0) os[row] = a;
    }
    __syncthreads();

    // O projection + residual: yfin[h] = os . wo[h,:] + 2*y0[h]
    {
        int h = tid >> 1, half = tid & 1;
        const float4* wor = (const float4*)(wo + (size_t)h * HH) + half * 32;
        const float4* osr = (const float4*)os + half * 32;
        float a = 0.f;
        #pragma unroll
        for (int c = 0; c < 32; c++) {
            float4 w = wor[c]; float4 o = osr[c];
            a += w.x * o.x + w.y * o.y + w.z * o.z + w.w * o.w;
        }
        a += __shfl_xor_sync(~0u, a, 1);
        if (half == 0) g_yfin[b * HH + h] = a + 2.f * g_y0[h];
    }
}

// ---------------- out[b, v] = yfin[b] . wu[v] ---------------------------------
__global__ void __launch_bounds__(256) k_out(const float* __restrict__ wu,
                                             float* __restrict__ out) {
    __shared__ __align__(16) float yf[BB * HH];   // 8 KB
    int tid = threadIdx.x;
    for (int i = tid; i < BB * HH; i += 256) yf[i] = g_yfin[i];
    __syncthreads();

    int v = blockIdx.x * 256 + tid;
    if (v >= VV) return;

    const float4* wur = (const float4*)(wu + (size_t)v * HH);
    const float4* yf4 = (const float4*)yf;
    float acc[8] = {0.f, 0.f, 0.f, 0.f, 0.f, 0.f, 0.f, 0.f};
    #pragma unroll
    for (int cc = 0; cc < 64; cc += 8) {
        float4 w[8];
        #pragma unroll
        for (int j = 0; j < 8; j++) w[j] = wur[cc + j];
        #pragma unroll
        for (int j = 0; j < 8; j++) {
            #pragma unroll
            for (int b = 0; b < 8; b++) {
                float4 y = yf4[b * 64 + cc + j];
                acc[b] += w[j].x * y.x + w[j].y * y.y + w[j].z * y.z + w[j].w * y.w;
            }
        }
    }
    #pragma unroll
    for (int b = 0; b < 8; b++) out[(size_t)b * VV + v] = acc[b];
}

// ---------------- launcher ----------------------------------------------------
extern "C" void kernel_launch(void* const* d_in, const int* in_sizes, int n_in,
                              void* d_out, int out_size) {
    const void*  x   = d_in[0];
    const float* emb = (const float*)d_in[1];
    const float* wq  = (const float*)d_in[2];
    const float* wk  = (const float*)d_in[3];
    const float* wv  = (const float*)d_in[4];
    const float* wo  = (const float*)d_in[5];
    const float* wu  = (const float*)d_in[6];
    float* out = (float*)d_out;

    k_init<<<NH + 1, 256>>>((const unsigned int*)x, emb, wq, wk);
    k_mid<<<LL + (VV + 15) / 16, 256>>>(emb);
    k_ybar<<<dim3(NCH, BB), 256>>>(x, emb);
    k_ov<<<BB, 512>>>(wv, wo);
    k_out<<<(VV + 255) / 256, 256>>>(wu, out);
}

// round 6
// speedup vs baseline: 1.2588x; 1.2588x over previous
#include <cuda_runtime.h>

// Problem constants
#define BB   8
#define SEQ  2047
#define LL   2048     // SEQ + 1 (CLS prepended)
#define HH   256
#define NH   8
#define DD   32
#define VV   32001
#define NCH  32       // t-chunks for ybar
#define CHT  64       // tokens per chunk

// ---------------- scratch (static device globals; no allocation) -------------
__device__ int   g_is64;
__device__ float g_pe[LL * HH];                 // 2 MB positional encoding
__device__ float g_qk[NH * HH];                 // per-head folded query vectors (scaled)
__device__ float g_y0[HH];                      // y at position 0 (same for all b)
__device__ float g_se[VV * NH];                 // ~1 MB: qk . emb[v], layout [v][n]
__device__ float g_pescT[LL * NH];              // qk . pe[t], layout [t][n]
__device__ float g_zp[BB * NH * NCH];           // partition-function partials
__device__ float g_ybp[NCH * BB * NH * HH];     // weighted-sum partials (2 MB)
__device__ float g_o[BB * HH];                  // attention output per batch
__device__ float g_yfin[BB * HH];               // final hidden at position 0

// ---------------- fused: dtype detect (block 8) + per-head prep (blocks 0-7) --
__global__ void k_init(const unsigned int* __restrict__ xw,
                       const float* __restrict__ emb,
                       const float* __restrict__ wq,
                       const float* __restrict__ wk) {
    int blk = blockIdx.x;
    int tid = threadIdx.x;       // 256

    if (blk == NH) {             // ---- dtype detection ----
        __shared__ int bad;
        if (tid == 0) bad = 0;
        __syncthreads();
        for (int i = tid; i < 1024; i += 256)
            if (xw[2 * i + 1] != 0u) bad = 1;
        __syncthreads();
        if (tid == 0) g_is64 = bad ? 0 : 1;
        return;
    }

    int n = blk;
    __shared__ float y0s[HH];
    __shared__ float q0s[DD];

    float y0 = emb[2 * HH + tid] + ((tid & 1) ? 1.0f : 0.0f);   // pe[0]=[0,1,0,1..]
    y0s[tid] = y0;
    if (n == 0) g_y0[tid] = y0;
    __syncthreads();

    if (tid < DD) {
        const float* wqr = wq + (size_t)(n * DD + tid) * HH;
        float a = 0.f;
        #pragma unroll 8
        for (int h = 0; h < HH; h++) a += y0s[h] * wqr[h];
        q0s[tid] = a;
    }
    __syncthreads();

    const float scale = 0.17677669529663687f;   // 1/sqrt(32)
    float s = 0.f;
    #pragma unroll
    for (int k = 0; k < DD; k++)
        s += q0s[k] * wk[(size_t)(n * DD + k) * HH + tid];
    g_qk[n * HH + tid] = s * scale;
}

// ---------------- fused: pe table + pescT (blocks < LL) + se GEMV (rest) ------
// se: 32 vocab rows per block, 4 per warp (MLP 8).
__global__ void __launch_bounds__(256) k_mid(const float* __restrict__ emb) {
    int tid = threadIdx.x, lane = tid & 31, warp = tid >> 5;

    if (blockIdx.x < LL) {
        int t = blockIdx.x;
        __shared__ float row[HH];
        if (tid < 128) {
            float div = expf(-(float)(2 * tid) * 0.03597789203f);   // ln(10000)/256
            float s, c;
            sincosf((float)t * div, &s, &c);
            row[2 * tid]     = s;
            row[2 * tid + 1] = c;
            g_pe[(size_t)t * HH + 2 * tid]     = s;
            g_pe[(size_t)t * HH + 2 * tid + 1] = c;
        }
        __syncthreads();
        int n = warp;
        float p = 0.f;
        #pragma unroll
        for (int j = lane; j < HH; j += 32) p += g_qk[n * HH + j] * row[j];
        #pragma unroll
        for (int off = 16; off; off >>= 1) p += __shfl_xor_sync(~0u, p, off);
        if (lane == 0) g_pescT[t * NH + n] = p;
        return;
    }

    __shared__ float qks[NH * HH];
    for (int i = tid; i < NH * HH; i += 256) qks[i] = g_qk[i];
    __syncthreads();

    int vb = (blockIdx.x - LL) * 32 + warp * 4;   // four rows per warp
    if (vb >= VV) return;

    float4 av[4], bv[4];
    #pragma unroll
    for (int r = 0; r < 4; r++) {
        int v = vb + r < VV ? vb + r : vb;
        const float4* e4 = (const float4*)(emb + (size_t)v * HH);
        av[r] = e4[lane];
        bv[r] = e4[lane + 32];
    }

    float p[4][8];
    #pragma unroll
    for (int n = 0; n < 8; n++) {
        const float4* q4 = (const float4*)(qks + n * HH);
        float4 qa = q4[lane], qb = q4[lane + 32];
        #pragma unroll
        for (int r = 0; r < 4; r++) {
            p[r][n] = av[r].x * qa.x + av[r].y * qa.y + av[r].z * qa.z + av[r].w * qa.w
                    + bv[r].x * qb.x + bv[r].y * qb.y + bv[r].z * qb.z + bv[r].w * qb.w;
        }
    }
    // funnel each row: 8 values x 32 lanes -> 5 shuffles
    #pragma unroll
    for (int r = 0; r < 4; r++) {
        #pragma unroll
        for (int n = 0; n < 4; n++) {
            bool hi = (lane & 8) != 0;
            float k = hi ? p[r][n + 4] : p[r][n];
            float s = hi ? p[r][n] : p[r][n + 4];
            p[r][n] = k + __shfl_xor_sync(~0u, s, 8);
        }
        #pragma unroll
        for (int n = 0; n < 2; n++) {
            bool hi = (lane & 4) != 0;
            float k = hi ? p[r][n + 2] : p[r][n];
            float s = hi ? p[r][n] : p[r][n + 2];
            p[r][n] = k + __shfl_xor_sync(~0u, s, 4);
        }
        {
            bool hi = (lane & 2) != 0;
            float k = hi ? p[r][1] : p[r][0];
            float s = hi ? p[r][0] : p[r][1];
            p[r][0] = k + __shfl_xor_sync(~0u, s, 2);
        }
        p[r][0] += __shfl_xor_sync(~0u, p[r][0], 16);
        p[r][0] += __shfl_xor_sync(~0u, p[r][0], 1);
    }
    // head-h total at lane h*2; lanes r*8..r*8+7 write row vb+r
    float res[4];
    #pragma unroll
    for (int r = 0; r < 4; r++)
        res[r] = __shfl_sync(~0u, p[r][0], (lane & 7) * 2);
    int r = lane >> 3;
    int v = vb + r;
    if (v < VV) g_se[(size_t)v * NH + (lane & 7)] = res[r];
}

// ---------------- fused scores+exp+weighted-sum partials ----------------------
// grid (NCH chunks, BB batches), 256 threads
__global__ void __launch_bounds__(256) k_ybar(const void* __restrict__ xraw,
                                              const float* __restrict__ emb) {
    __shared__ float A8[8][CHT];
    __shared__ int toks[CHT];
    int tid = threadIdx.x, lane = tid & 31, warp = tid >> 5;
    int ch = blockIdx.x;
    int b  = blockIdx.y;
    int c0 = ch * CHT;
    int is64 = g_is64;

    // Phase A: tokens, scores, exp (unnormalized; scores are O(1), safe)
    if (tid < CHT) {
        int t = c0 + tid;
        int tok;
        if (t == 0) tok = 2;
        else if (is64) tok = (int)((const long long*)xraw)[(size_t)b * SEQ + t - 1];
        else           tok = ((const int*)xraw)[(size_t)b * SEQ + t - 1];
        toks[tid] = tok;

        const float4* se4 = (const float4*)(g_se + (size_t)tok * NH);
        const float4* pp4 = (const float4*)(g_pescT + (size_t)t * NH);
        float4 s0 = se4[0], s1 = se4[1];
        float4 p0 = pp4[0], p1 = pp4[1];
        A8[0][tid] = expf(s0.x + p0.x);
        A8[1][tid] = expf(s0.y + p0.y);
        A8[2][tid] = expf(s0.z + p0.z);
        A8[3][tid] = expf(s0.w + p0.w);
        A8[4][tid] = expf(s1.x + p1.x);
        A8[5][tid] = expf(s1.y + p1.y);
        A8[6][tid] = expf(s1.z + p1.z);
        A8[7][tid] = expf(s1.w + p1.w);
    }
    __syncthreads();

    // Phase B: per-head partition partials (warp n reduces A8[n][:])
    {
        float z = A8[warp][lane] + A8[warp][lane + 32];
        #pragma unroll
        for (int off = 16; off; off >>= 1) z += __shfl_xor_sync(~0u, z, off);
        if (lane == 0) g_zp[((size_t)b * NH + warp) * NCH + ch] = z;
    }

    // Phase C: weighted sums over tokens (tid = h), 8-deep load batching
    int h = tid;
    float acc[8] = {0.f, 0.f, 0.f, 0.f, 0.f, 0.f, 0.f, 0.f};
    #pragma unroll
    for (int tt = 0; tt < CHT; tt += 8) {
        float ev[8], pv[8];
        #pragma unroll
        for (int j = 0; j < 8; j++) {
            ev[j] = emb[(size_t)toks[tt + j] * HH + h];
            pv[j] = g_pe[(size_t)(c0 + tt + j) * HH + h];
        }
        #pragma unroll
        for (int j = 0; j < 8; j++) {
            float y = ev[j] + pv[j];
            #pragma unroll
            for (int n = 0; n < 8; n++) acc[n] += A8[n][tt + j] * y;
        }
    }
    #pragma unroll
    for (int n = 0; n < 8; n++)
        g_ybp[((size_t)ch * BB + b) * (NH * HH) + n * HH + h] = acc[n];
}

// ---------------- k_ova: per-(b,n) reduce+normalize, o-slice = ybar @ wv^T ----
// grid 64 = b*NH + n, 512 threads
__global__ void __launch_bounds__(512) k_ova(const float* __restrict__ wv) {
    __shared__ __align__(16) float ybs[HH];
    __shared__ float part[HH];
    __shared__ float zinv_s;
    int tid = threadIdx.x, lane = tid & 31, warp = tid >> 5;
    int bn = blockIdx.x;
    int b = bn >> 3, n = bn & 7;

    // partition function (NCH == 32 == warp size)
    if (warp == 0) {
        float z = g_zp[(size_t)bn * NCH + lane];
        #pragma unroll
        for (int off = 16; off; off >>= 1) z += __shfl_xor_sync(~0u, z, off);
        if (lane == 0) zinv_s = 1.f / z;
    }

    // reduce ybp over chunks: 2 thread-groups x 16 chunks, 8-deep batching
    int h = tid & 255, hc = tid >> 8;    // hc in {0,1}
    float s = 0.f;
    #pragma unroll
    for (int cg = 0; cg < 16; cg += 8) {
        float v[8];
        #pragma unroll
        for (int j = 0; j < 8; j++)
            v[j] = g_ybp[((size_t)(hc * 16 + cg + j) * BB + b) * (NH * HH) + n * HH + h];
        #pragma unroll
        for (int j = 0; j < 8; j++) s += v[j];
    }
    if (hc == 1) part[h] = s;
    __syncthreads();
    if (hc == 0) ybs[h] = (s + part[h]) * zinv_s;
    __syncthreads();

    // o[b, n*32+k] = ybar . wv[n,k,:]   (16 threads per k, 4 float4 each)
    int k = tid >> 4, g = tid & 15;
    const float4* wvr = (const float4*)(wv + (size_t)(n * DD + k) * HH);
    const float4* yb4 = (const float4*)ybs;
    float a = 0.f;
    #pragma unroll
    for (int c = 0; c < 4; c++) {
        float4 w = wvr[g * 4 + c]; float4 y = yb4[g * 4 + c];
        a += w.x * y.x + w.y * y.y + w.z * y.z + w.w * y.w;
    }
    a += __shfl_xor_sync(~0u, a, 8);
    a += __shfl_xor_sync(~0u, a, 4);
    a += __shfl_xor_sync(~0u, a, 2);
    a += __shfl_xor_sync(~0u, a, 1);
    if (g == 0) g_o[b * HH + n * DD + k] = a;
}

// ---------------- k_ovb: yfin = o @ wo^T + 2*y0 -------------------------------
// grid 64 = b*8 + hc, 256 threads; each block does 32 h-outputs
__global__ void __launch_bounds__(256) k_ovb(const float* __restrict__ wo) {
    __shared__ __align__(16) float os[HH];
    int tid = threadIdx.x;
    int blk = blockIdx.x;
    int b = blk >> 3, hc = blk & 7;

    if (tid < HH) os[tid] = g_o[b * HH + tid];
    __syncthreads();

    int i = tid >> 3, g = tid & 7;       // h = hc*32 + i
    int h = hc * 32 + i;
    const float4* wor = (const float4*)(wo + (size_t)h * HH);
    const float4* o4 = (const float4*)os;
    float a = 0.f;
    #pragma unroll
    for (int c = 0; c < 8; c++) {
        float4 w = wor[g * 8 + c]; float4 o = o4[g * 8 + c];
        a += w.x * o.x + w.y * o.y + w.z * o.z + w.w * o.w;
    }
    a += __shfl_xor_sync(~0u, a, 4);
    a += __shfl_xor_sync(~0u, a, 2);
    a += __shfl_xor_sync(~0u, a, 1);
    if (g == 0) g_yfin[b * HH + h] = a + 2.f * g_y0[h];
}

// ---------------- out[b, v] = yfin[b] . wu[v] ---------------------------------
__global__ void __launch_bounds__(256) k_out(const float* __restrict__ wu,
                                             float* __restrict__ out) {
    __shared__ __align__(16) float yf[BB * HH];   // 8 KB
    int tid = threadIdx.x;
    for (int i = tid; i < BB * HH; i += 256) yf[i] = g_yfin[i];
    __syncthreads();

    int v = blockIdx.x * 256 + tid;
    if (v >= VV) return;

    const float4* wur = (const float4*)(wu + (size_t)v * HH);
    const float4* yf4 = (const float4*)yf;
    float acc[8] = {0.f, 0.f, 0.f, 0.f, 0.f, 0.f, 0.f, 0.f};
    #pragma unroll
    for (int cc = 0; cc < 64; cc += 8) {
        float4 w[8];
        #pragma unroll
        for (int j = 0; j < 8; j++) w[j] = wur[cc + j];
        #pragma unroll
        for (int j = 0; j < 8; j++) {
            #pragma unroll
            for (int b = 0; b < 8; b++) {
                float4 y = yf4[b * 64 + cc + j];
                acc[b] += w[j].x * y.x + w[j].y * y.y + w[j].z * y.z + w[j].w * y.w;
            }
        }
    }
    #pragma unroll
    for (int b = 0; b < 8; b++) out[(size_t)b * VV + v] = acc[b];
}

// ---------------- launcher ----------------------------------------------------
extern "C" void kernel_launch(void* const* d_in, const int* in_sizes, int n_in,
                              void* d_out, int out_size) {
    const void*  x   = d_in[0];
    const float* emb = (const float*)d_in[1];
    const float* wq  = (const float*)d_in[2];
    const float* wk  = (const float*)d_in[3];
    const float* wv  = (const float*)d_in[4];
    const float* wo  = (const float*)d_in[5];
    const float* wu  = (const float*)d_in[6];
    float* out = (float*)d_out;

    k_init<<<NH + 1, 256>>>((const unsigned int*)x, emb, wq, wk);
    k_mid<<<LL + (VV + 31) / 32, 256>>>(emb);
    k_ybar<<<dim3(NCH, BB), 256>>>(x, emb);
    k_ova<<<BB * NH, 512>>>(wv);
    k_ovb<<<BB * NH, 256>>>(wo);
    k_out<<<(VV + 255) / 256, 256>>>(wu, out);
}